// round 3
// baseline (speedup 1.0000x reference)
#include <cuda_runtime.h>

// Problem constants
#define BATCH 8
#define NCLS 19
#define HH 768
#define WW 768
#define HWP (HH * WW)                 // 589824
#define HWP2 (HWP / 2)                // 294912
#define N_PIX (BATCH * HWP)           // 4718592
#define N_PAIR (N_PIX / 2)            // 2359296
#define N4 (N_PIX / 4)                // 1179648
#define IGNORE_LBL 255
#define MIN_KEPT_K 262144u
#define THRESH_F 0.7f
#define ONE_BITS 0x3F800000u
#define ALMOST_ONE_BITS 0x3F7FFFFFu

// Scratch (no cudaMalloc allowed)
__device__ float g_prob[N_PIX];                // 18.9 MB (valid-encoded: 1.0f == invalid)
__device__ unsigned int g_hA[65536];           // hist of bits 31..16
__device__ unsigned int g_hB[65536];           // hist of bits 15..0 (prefix-filtered)
__device__ unsigned int g_prefix_hi;           // winning hi-16 bin
__device__ unsigned int g_kth_bits;            // full 32-bit pattern of kth value
__device__ unsigned int g_k;
__device__ unsigned int g_num_valid;
__device__ unsigned int g_done;
__device__ double g_sum;
__device__ unsigned int g_cnt;

// ---------------------------------------------------------------------------
__global__ void init_kernel() {
    int gtid = blockIdx.x * blockDim.x + threadIdx.x;
    if (gtid < 65536) g_hA[gtid] = 0u;
    else if (gtid < 131072) g_hB[gtid - 65536] = 0u;
    if (gtid == 0) {
        g_prefix_hi = 0u;
        g_kth_bits = 0u;
        g_k = MIN_KEPT_K;   // k = min(N, MIN_KEPT) = MIN_KEPT since N > MIN_KEPT
        g_num_valid = 0u;
        g_done = 0u;
        g_sum = 0.0;
        g_cnt = 0u;
    }
}

// ---------------------------------------------------------------------------
// Main pass: log-softmax over 19 channels (2 pixels/thread via float2), gather
// at target class, write valid-encoded prob, fused hi-16 radix histogram.
__global__ void __launch_bounds__(256) main_pass(const float* __restrict__ pred,
                                                 const int* __restrict__ target) {
    const int stride = gridDim.x * blockDim.x;
    unsigned int vcnt = 0;

    for (int i2 = blockIdx.x * blockDim.x + threadIdx.x; i2 < N_PAIR; i2 += stride) {
        int b = i2 / HWP2;
        int hw2 = i2 - b * HWP2;
        const float2* p = reinterpret_cast<const float2*>(pred + (size_t)b * NCLS * HWP) + hw2;

        int2 tt = reinterpret_cast<const int2*>(target)[i2];
        bool v0 = (tt.x != IGNORE_LBL);
        bool v1 = (tt.y != IGNORE_LBL);
        int tc0 = v0 ? tt.x : 0;
        int tc1 = v1 ? tt.y : 0;

        float2 vals[NCLS];
        float m0 = -1e30f, m1 = -1e30f;
        float vt0 = 0.0f, vt1 = 0.0f;
#pragma unroll
        for (int c = 0; c < NCLS; c++) {
            float2 x = p[c * HWP2];
            vals[c] = x;
            m0 = fmaxf(m0, x.x);
            m1 = fmaxf(m1, x.y);
            if (c == tc0) vt0 = x.x;     // predicated selects, no dynamic indexing
            if (c == tc1) vt1 = x.y;
        }
        float s0 = 0.0f, s1 = 0.0f;
#pragma unroll
        for (int c = 0; c < NCLS; c++) {
            s0 += __expf(vals[c].x - m0);
            s1 += __expf(vals[c].y - m1);
        }

        float pr0, pr1;
        if (v0) {
            pr0 = __expf(vt0 - m0 - __logf(s0));
            // valid pixels may never encode as exactly 1.0f (1.0f == invalid marker)
            unsigned int bb = __float_as_uint(pr0);
            if (bb >= ONE_BITS) bb = ALMOST_ONE_BITS;
            pr0 = __uint_as_float(bb);
        } else pr0 = 1.0f;
        if (v1) {
            pr1 = __expf(vt1 - m1 - __logf(s1));
            unsigned int bb = __float_as_uint(pr1);
            if (bb >= ONE_BITS) bb = ALMOST_ONE_BITS;
            pr1 = __uint_as_float(bb);
        } else pr1 = 1.0f;

        reinterpret_cast<float2*>(g_prob)[i2] = make_float2(pr0, pr1);
        vcnt += (v0 ? 1u : 0u) + (v1 ? 1u : 0u);

        // fused radix round 1: 64K-bin hist of bits 31..16, warp-aggregated
        unsigned int bin0 = __float_as_uint(pr0) >> 16;
        unsigned int bin1 = __float_as_uint(pr1) >> 16;
        unsigned int am = __activemask();
        int lane = threadIdx.x & 31;
        unsigned int mm0 = __match_any_sync(am, bin0);
        if (lane == __ffs(mm0) - 1) atomicAdd(&g_hA[bin0], (unsigned int)__popc(mm0));
        unsigned int mm1 = __match_any_sync(am, bin1);
        if (lane == __ffs(mm1) - 1) atomicAdd(&g_hA[bin1], (unsigned int)__popc(mm1));
    }

    // block-reduce vcnt
    __shared__ unsigned int sh[32];
    int lane = threadIdx.x & 31, wid = threadIdx.x >> 5;
#pragma unroll
    for (int o = 16; o; o >>= 1) vcnt += __shfl_down_sync(0xffffffffu, vcnt, o);
    if (lane == 0) sh[wid] = vcnt;
    __syncthreads();
    if (wid == 0) {
        unsigned int v = (lane < (blockDim.x >> 5)) ? sh[lane] : 0u;
#pragma unroll
        for (int o = 16; o; o >>= 1) v += __shfl_down_sync(0xffffffffu, v, o);
        if (lane == 0) atomicAdd(&g_num_valid, v);
    }
}

// ---------------------------------------------------------------------------
// Scan 64K-bin histogram with 1024 threads (64 bins each). PHASE 0: find hi-16
// digit, rebase k. PHASE 1: find lo-16 digit, emit full kth bit pattern.
template <int PHASE>
__global__ void __launch_bounds__(1024) scan16_kernel() {
    const unsigned int* hist = (PHASE == 0) ? g_hA : g_hB;
    __shared__ unsigned int s[1024];
    int t = threadIdx.x;
    int base = t * 64;

    unsigned int lsum = 0;
    const uint4* h4 = reinterpret_cast<const uint4*>(hist);
#pragma unroll
    for (int j = 0; j < 16; j++) {
        uint4 u = h4[(base >> 2) + j];
        lsum += u.x + u.y + u.z + u.w;
    }
    s[t] = lsum;
    __syncthreads();
#pragma unroll
    for (int o = 1; o < 1024; o <<= 1) {
        unsigned int v = (t >= o) ? s[t - o] : 0u;
        __syncthreads();
        s[t] += v;
        __syncthreads();
    }
    unsigned int k = g_k;
    unsigned int incl = s[t];
    unsigned int excl = incl - lsum;
    if (excl < k && k <= incl && lsum > 0) {
        unsigned int cum = excl;
        for (int b = 0; b < 64; b++) {
            unsigned int c = hist[base + b];
            cum += c;
            if (cum >= k) {
                if (PHASE == 0) {
                    g_prefix_hi = (unsigned int)(base + b);
                    g_k = k - (cum - c);
                } else {
                    g_kth_bits = (g_prefix_hi << 16) | (unsigned int)(base + b);
                }
                break;
            }
        }
    }
}

// ---------------------------------------------------------------------------
// Round 2: histogram the low 16 bits of elements whose hi-16 match the prefix.
// Grid sized so 4 * (gridDim*blockDim) == N4: 4 independent loads in flight.
__global__ void __launch_bounds__(256) hist_lo_pass() {
    unsigned int prefix = g_prefix_hi;
    const uint4* p4 = reinterpret_cast<const uint4*>(g_prob);
    const int T = gridDim.x * blockDim.x;
    int i = blockIdx.x * blockDim.x + threadIdx.x;

    uint4 v[4];
#pragma unroll
    for (int j = 0; j < 4; j++) {
        int idx = i + j * T;
        v[j] = (idx < N4) ? p4[idx] : make_uint4(0, 0, 0, 0);
    }
#pragma unroll
    for (int j = 0; j < 4; j++) {
        if (i + j * T >= N4) break;
        unsigned int bb[4] = {v[j].x, v[j].y, v[j].z, v[j].w};
#pragma unroll
        for (int e = 0; e < 4; e++)
            if ((bb[e] >> 16) == prefix) atomicAdd(&g_hB[bb[e] & 0xFFFFu], 1u);
    }
}

// ---------------------------------------------------------------------------
// Final reduce: sum -log(prob) over kept pixels (validity encoded in prob).
// Last block writes the output.
__global__ void __launch_bounds__(256) final_pass(float* __restrict__ out) {
    float kth = __uint_as_float(g_kth_bits);
    float thr = fmaxf(kth, THRESH_F);
    bool do_ohem = (g_num_valid >= MIN_KEPT_K);  // implies num_valid > 0

    const float4* p4 = reinterpret_cast<const float4*>(g_prob);
    const int T = gridDim.x * blockDim.x;
    int i = blockIdx.x * blockDim.x + threadIdx.x;

    float4 v[4];
#pragma unroll
    for (int j = 0; j < 4; j++) {
        int idx = i + j * T;
        v[j] = (idx < N4) ? p4[idx] : make_float4(1.0f, 1.0f, 1.0f, 1.0f);
    }

    float lsum = 0.0f;
    unsigned int cnt = 0;
#pragma unroll
    for (int j = 0; j < 4; j++) {
        float pr[4] = {v[j].x, v[j].y, v[j].z, v[j].w};
#pragma unroll
        for (int e = 0; e < 4; e++) {
            bool valid = (__float_as_uint(pr[e]) != ONE_BITS);
            bool keep = valid && (!do_ohem || pr[e] <= thr);
            if (keep) {
                lsum += -__logf(pr[e]);
                cnt++;
            }
        }
    }

    // block reductions (float sum + uint count)
    __shared__ float shf[32];
    __shared__ unsigned int shu[32];
    int lane = threadIdx.x & 31, wid = threadIdx.x >> 5;
#pragma unroll
    for (int o = 16; o; o >>= 1) {
        lsum += __shfl_down_sync(0xffffffffu, lsum, o);
        cnt += __shfl_down_sync(0xffffffffu, cnt, o);
    }
    if (lane == 0) { shf[wid] = lsum; shu[wid] = cnt; }
    __syncthreads();

    __shared__ bool is_last;
    if (threadIdx.x == 0) is_last = false;
    __syncthreads();

    if (wid == 0) {
        float vv = (lane < (blockDim.x >> 5)) ? shf[lane] : 0.0f;
        unsigned int u = (lane < (blockDim.x >> 5)) ? shu[lane] : 0u;
#pragma unroll
        for (int o = 16; o; o >>= 1) {
            vv += __shfl_down_sync(0xffffffffu, vv, o);
            u += __shfl_down_sync(0xffffffffu, u, o);
        }
        if (lane == 0) {
            atomicAdd(&g_sum, (double)vv);
            atomicAdd(&g_cnt, u);
            __threadfence();
            unsigned int done = atomicAdd(&g_done, 1u);
            if (done == gridDim.x - 1) is_last = true;
        }
    }
    __syncthreads();
    if (is_last && threadIdx.x == 0) {
        unsigned int c = g_cnt;
        if (c < 1u) c = 1u;
        out[0] = (float)(g_sum / (double)c);
    }
}

// ---------------------------------------------------------------------------
extern "C" void kernel_launch(void* const* d_in, const int* in_sizes, int n_in,
                              void* d_out, int out_size) {
    const float* pred = (const float*)d_in[0];
    const int* target = (const int*)d_in[1];
    float* out = (float*)d_out;

    init_kernel<<<256, 512>>>();
    main_pass<<<1184, 256>>>(pred, target);   // fused hi-16 radix histogram
    scan16_kernel<0><<<1, 1024>>>();
    hist_lo_pass<<<1152, 256>>>();            // 1152*256*4 == N4 exactly
    scan16_kernel<1><<<1, 1024>>>();
    final_pass<<<1152, 256>>>(out);
}

// round 4
// speedup vs baseline: 7.9232x; 7.9232x over previous
#include <cuda_runtime.h>

// Problem constants
#define BATCH 8
#define NCLS 19
#define HH 768
#define WW 768
#define HWP (HH * WW)                 // 589824
#define N_PIX (BATCH * HWP)           // 4718592
#define N4 (N_PIX / 4)                // 1179648
#define IGNORE_LBL 255
#define MIN_KEPT_K 262144u
#define THRESH_F 0.7f
#define ONE_BITS 0x3F800000u
#define ALMOST_ONE_BITS 0x3F7FFFFFu

// Scratch (no cudaMalloc allowed)
__device__ float g_prob[N_PIX];                // 18.9 MB (valid-encoded: 1.0f bits == invalid)
__device__ unsigned int g_h256[256];           // round-1 hist (bits 31..24), fused in main
__device__ unsigned int g_h16[65536];          // round-2 hist (bits 23..8), prefix-filtered
__device__ unsigned int g_prefix;              // accumulated kth-bit prefix
__device__ unsigned int g_kth_bits;            // full 32-bit pattern of kth value (0 if skipped)
__device__ unsigned int g_k;
__device__ unsigned int g_skip;                // 1 => threshold is 0.7, skip refinement
__device__ unsigned int g_c07;                 // count of mask_prob <= 0.7
__device__ unsigned int g_num_valid;
__device__ unsigned int g_done;
__device__ double g_sum;
__device__ unsigned int g_cnt;

// ---------------------------------------------------------------------------
__global__ void init_kernel() {
    int gtid = blockIdx.x * blockDim.x + threadIdx.x;
    if (gtid < 65536) g_h16[gtid] = 0u;
    if (gtid < 256) g_h256[gtid] = 0u;
    if (gtid == 0) {
        g_prefix = 0u;
        g_kth_bits = 0u;
        g_k = MIN_KEPT_K;   // k = min(N, MIN_KEPT) = MIN_KEPT since N > MIN_KEPT
        g_skip = 0u;
        g_c07 = 0u;
        g_num_valid = 0u;
        g_done = 0u;
        g_sum = 0.0;
        g_cnt = 0u;
    }
}

// ---------------------------------------------------------------------------
// Main pass (R2-proven scalar form): log-softmax over 19 channels, gather at
// target class, write valid-encoded prob, fused 256-bin exponent histogram
// (warp-aggregated — probs cluster into few exponent bins) + c07 count.
__global__ void __launch_bounds__(256) main_pass(const float* __restrict__ pred,
                                                 const int* __restrict__ target) {
    __shared__ unsigned int shh[256];
    if (threadIdx.x < 256) shh[threadIdx.x] = 0u;
    __syncthreads();

    const int stride = gridDim.x * blockDim.x;
    unsigned int vcnt = 0;
    unsigned int c07 = 0;

    for (int i = blockIdx.x * blockDim.x + threadIdx.x; i < N_PIX; i += stride) {
        int b = i / HWP;
        int hw = i - b * HWP;
        const float* p = pred + (size_t)b * (NCLS * HWP) + hw;

        int t = target[i];
        bool valid = (t != IGNORE_LBL);
        int tc = valid ? t : 0;

        float vals[NCLS];
        float m = -1e30f;
        float vt = 0.0f;
#pragma unroll
        for (int c = 0; c < NCLS; c++) {
            float x = p[c * HWP];
            vals[c] = x;
            m = fmaxf(m, x);
            if (c == tc) vt = x;      // predicated select, no dynamic indexing
        }
        float s = 0.0f;
#pragma unroll
        for (int c = 0; c < NCLS; c++) s += __expf(vals[c] - m);

        float pr;
        if (valid) {
            pr = __expf(vt - m - __logf(s));
            // valid pixels may never encode as exactly 1.0f (== invalid marker)
            unsigned int bb = __float_as_uint(pr);
            if (bb >= ONE_BITS) bb = ALMOST_ONE_BITS;
            pr = __uint_as_float(bb);
        } else {
            pr = 1.0f;
        }
        g_prob[i] = pr;
        vcnt += valid ? 1u : 0u;
        c07 += (pr <= THRESH_F) ? 1u : 0u;

        // warp-aggregated shared hist of the exponent byte
        unsigned int bin = __float_as_uint(pr) >> 24;
        unsigned int am = __activemask();
        unsigned int mmask = __match_any_sync(am, bin);
        int leader = __ffs(mmask) - 1;
        if ((int)(threadIdx.x & 31) == leader)
            atomicAdd(&shh[bin], (unsigned int)__popc(mmask));
    }

    // block-reduce vcnt + c07
    __shared__ unsigned int sh[32];
    __shared__ unsigned int sh2[32];
    int lane = threadIdx.x & 31, wid = threadIdx.x >> 5;
#pragma unroll
    for (int o = 16; o; o >>= 1) {
        vcnt += __shfl_down_sync(0xffffffffu, vcnt, o);
        c07  += __shfl_down_sync(0xffffffffu, c07, o);
    }
    if (lane == 0) { sh[wid] = vcnt; sh2[wid] = c07; }
    __syncthreads();
    if (wid == 0) {
        unsigned int v = (lane < (blockDim.x >> 5)) ? sh[lane] : 0u;
        unsigned int w = (lane < (blockDim.x >> 5)) ? sh2[lane] : 0u;
#pragma unroll
        for (int o = 16; o; o >>= 1) {
            v += __shfl_down_sync(0xffffffffu, v, o);
            w += __shfl_down_sync(0xffffffffu, w, o);
        }
        if (lane == 0) {
            atomicAdd(&g_num_valid, v);
            atomicAdd(&g_c07, w);
        }
    }

    // merge shared hist
    unsigned int c = shh[threadIdx.x];
    if (c) atomicAdd(&g_h256[threadIdx.x], c);
}

// ---------------------------------------------------------------------------
// Scan round-1 (256 exponent bins); also decide whether refinement is needed.
__global__ void scanA_kernel() {
    __shared__ unsigned int s[256];
    int t = threadIdx.x;
    unsigned int c = g_h256[t];
    s[t] = c;
    __syncthreads();
#pragma unroll
    for (int o = 1; o < 256; o <<= 1) {
        unsigned int v = (t >= o) ? s[t - o] : 0u;
        __syncthreads();
        s[t] += v;
        __syncthreads();
    }
    if (t == 0) g_skip = (g_c07 >= MIN_KEPT_K) ? 1u : 0u;  // kth <= 0.7 => thr = 0.7
    unsigned int k = g_k;
    unsigned int incl = s[t];
    unsigned int excl = incl - c;
    if (excl < k && k <= incl) {
        g_prefix = ((unsigned int)t) << 24;
        g_k = k - excl;
    }
    g_h256[t] = 0u;   // reused by round 3
}

// ---------------------------------------------------------------------------
// Round 2 (only if kth > 0.7): 16-bit hist (bits 23..8) filtered on hi-8 prefix.
__global__ void __launch_bounds__(256) hist_mid_pass() {
    if (g_skip) return;
    unsigned int prefix = g_prefix;   // top 8 bits set
    const uint4* p4 = reinterpret_cast<const uint4*>(g_prob);
    const int stride = gridDim.x * blockDim.x;
    for (int i = blockIdx.x * blockDim.x + threadIdx.x; i < N4; i += stride) {
        uint4 v = p4[i];
        if ((v.x & 0xFF000000u) == prefix) atomicAdd(&g_h16[(v.x >> 8) & 0xFFFFu], 1u);
        if ((v.y & 0xFF000000u) == prefix) atomicAdd(&g_h16[(v.y >> 8) & 0xFFFFu], 1u);
        if ((v.z & 0xFF000000u) == prefix) atomicAdd(&g_h16[(v.z >> 8) & 0xFFFFu], 1u);
        if ((v.w & 0xFF000000u) == prefix) atomicAdd(&g_h16[(v.w >> 8) & 0xFFFFu], 1u);
    }
}

// Scan 64K bins with 1024 threads (64 bins each).
__global__ void __launch_bounds__(1024) scan_mid_kernel() {
    if (g_skip) return;
    __shared__ unsigned int s[1024];
    int t = threadIdx.x;
    int base = t * 64;

    unsigned int lsum = 0;
    const uint4* h4 = reinterpret_cast<const uint4*>(g_h16);
#pragma unroll
    for (int j = 0; j < 16; j++) {
        uint4 u = h4[(base >> 2) + j];
        lsum += u.x + u.y + u.z + u.w;
    }
    s[t] = lsum;
    __syncthreads();
#pragma unroll
    for (int o = 1; o < 1024; o <<= 1) {
        unsigned int v = (t >= o) ? s[t - o] : 0u;
        __syncthreads();
        s[t] += v;
        __syncthreads();
    }
    unsigned int k = g_k;
    unsigned int incl = s[t];
    unsigned int excl = incl - lsum;
    if (excl < k && k <= incl && lsum > 0) {
        unsigned int cum = excl;
        for (int b = 0; b < 64; b++) {
            unsigned int c = g_h16[base + b];
            cum += c;
            if (cum >= k) {
                atomicOr(&g_prefix, ((unsigned int)(base + b)) << 8);
                g_k = k - (cum - c);
                break;
            }
        }
    }
}

// Round 3: low 8-bit histogram filtered on hi-24 prefix.
__global__ void __launch_bounds__(256) hist_lo_pass() {
    if (g_skip) return;
    __shared__ unsigned int shh[256];
    shh[threadIdx.x] = 0u;
    __syncthreads();

    unsigned int prefix = g_prefix;   // top 24 bits set
    const uint4* p4 = reinterpret_cast<const uint4*>(g_prob);
    const int stride = gridDim.x * blockDim.x;
    for (int i = blockIdx.x * blockDim.x + threadIdx.x; i < N4; i += stride) {
        uint4 v = p4[i];
        if ((v.x & 0xFFFFFF00u) == prefix) atomicAdd(&shh[v.x & 255u], 1u);
        if ((v.y & 0xFFFFFF00u) == prefix) atomicAdd(&shh[v.y & 255u], 1u);
        if ((v.z & 0xFFFFFF00u) == prefix) atomicAdd(&shh[v.z & 255u], 1u);
        if ((v.w & 0xFFFFFF00u) == prefix) atomicAdd(&shh[v.w & 255u], 1u);
    }
    __syncthreads();
    unsigned int c = shh[threadIdx.x];
    if (c) atomicAdd(&g_h256[threadIdx.x], c);
}

__global__ void scan_lo_kernel() {
    if (g_skip) return;
    __shared__ unsigned int s[256];
    int t = threadIdx.x;
    unsigned int c = g_h256[t];
    s[t] = c;
    __syncthreads();
#pragma unroll
    for (int o = 1; o < 256; o <<= 1) {
        unsigned int v = (t >= o) ? s[t - o] : 0u;
        __syncthreads();
        s[t] += v;
        __syncthreads();
    }
    unsigned int k = g_k;
    unsigned int incl = s[t];
    unsigned int excl = incl - c;
    if (excl < k && k <= incl) {
        g_kth_bits = g_prefix | (unsigned int)t;
    }
}

// ---------------------------------------------------------------------------
// Final reduce: sum -log(prob) over kept pixels (validity encoded in prob).
// thr = max(kth, 0.7); when refinement was skipped, kth_bits==0 => thr=0.7.
__global__ void __launch_bounds__(256) final_pass(float* __restrict__ out) {
    float kth = __uint_as_float(g_kth_bits);
    float thr = fmaxf(kth, THRESH_F);
    bool do_ohem = (g_num_valid >= MIN_KEPT_K);  // implies num_valid > 0

    const float4* p4 = reinterpret_cast<const float4*>(g_prob);
    const int T = gridDim.x * blockDim.x;
    int i = blockIdx.x * blockDim.x + threadIdx.x;

    float4 v[4];
#pragma unroll
    for (int j = 0; j < 4; j++) {
        int idx = i + j * T;
        v[j] = (idx < N4) ? p4[idx] : make_float4(1.0f, 1.0f, 1.0f, 1.0f);
    }

    float lsum = 0.0f;
    unsigned int cnt = 0;
#pragma unroll
    for (int j = 0; j < 4; j++) {
        float pr[4] = {v[j].x, v[j].y, v[j].z, v[j].w};
#pragma unroll
        for (int e = 0; e < 4; e++) {
            bool valid = (__float_as_uint(pr[e]) != ONE_BITS);
            bool keep = valid && (!do_ohem || pr[e] <= thr);
            if (keep) {
                lsum += -__logf(pr[e]);
                cnt++;
            }
        }
    }

    // block reductions (float sum + uint count)
    __shared__ float shf[32];
    __shared__ unsigned int shu[32];
    int lane = threadIdx.x & 31, wid = threadIdx.x >> 5;
#pragma unroll
    for (int o = 16; o; o >>= 1) {
        lsum += __shfl_down_sync(0xffffffffu, lsum, o);
        cnt += __shfl_down_sync(0xffffffffu, cnt, o);
    }
    if (lane == 0) { shf[wid] = lsum; shu[wid] = cnt; }
    __syncthreads();

    __shared__ bool is_last;
    if (threadIdx.x == 0) is_last = false;
    __syncthreads();

    if (wid == 0) {
        float vv = (lane < (blockDim.x >> 5)) ? shf[lane] : 0.0f;
        unsigned int u = (lane < (blockDim.x >> 5)) ? shu[lane] : 0u;
#pragma unroll
        for (int o = 16; o; o >>= 1) {
            vv += __shfl_down_sync(0xffffffffu, vv, o);
            u += __shfl_down_sync(0xffffffffu, u, o);
        }
        if (lane == 0) {
            atomicAdd(&g_sum, (double)vv);
            atomicAdd(&g_cnt, u);
            __threadfence();
            unsigned int done = atomicAdd(&g_done, 1u);
            if (done == gridDim.x - 1) is_last = true;
        }
    }
    __syncthreads();
    if (is_last && threadIdx.x == 0) {
        unsigned int c = g_cnt;
        if (c < 1u) c = 1u;
        out[0] = (float)(g_sum / (double)c);
    }
}

// ---------------------------------------------------------------------------
extern "C" void kernel_launch(void* const* d_in, const int* in_sizes, int n_in,
                              void* d_out, int out_size) {
    const float* pred = (const float*)d_in[0];
    const int* target = (const int*)d_in[1];
    float* out = (float*)d_out;

    init_kernel<<<64, 1024>>>();
    main_pass<<<1184, 256>>>(pred, target);   // fused exponent hist + c07 count
    scanA_kernel<<<1, 256>>>();               // digit 1 + skip decision
    hist_mid_pass<<<592, 256>>>();            // bits 23..8 (early-exit if skip)
    scan_mid_kernel<<<1, 1024>>>();
    hist_lo_pass<<<592, 256>>>();             // bits 7..0 (early-exit if skip)
    scan_lo_kernel<<<1, 256>>>();
    final_pass<<<1152, 256>>>(out);
}